// round 5
// baseline (speedup 1.0000x reference)
#include <cuda_runtime.h>
#include <math.h>
#include <stdint.h>

#define NB 16
#define NA 25200
#define NC 80
#define KPRE 256
#define MAXB 100
#define SORTN 1024
#define SORTF 256
#define NBINS 2048
#define SCORE_THR 0.25f
#define IOU_THR 0.1f

#define CELLS 40
#define ANCH (CELLS * 3)
#define STG (CELLS * 255)

// anchors: p5 (20x20) [0,1200), p4 (40x40) [1200,6000), p3 (80x80) [6000,25200)

__device__ float4 g_boxes[NB * NA];
__device__ float g_scores[(size_t)NB * NC * NA];
__device__ unsigned int g_rung[NB * NC * 16];
__device__ unsigned long long g_keys[NB * NC * KPRE];

__constant__ float c_anch[9][2] = {
    {116.f, 90.f}, {156.f, 198.f}, {373.f, 326.f},
    {30.f, 61.f},  {62.f, 45.f},   {59.f, 119.f},
    {10.f, 13.f},  {16.f, 30.f},   {33.f, 23.f}
};

__constant__ float c_rungs[16] = {
    0.97f, 0.93f, 0.88f, 0.82f, 0.76f, 0.70f, 0.64f, 0.58f,
    0.52f, 0.46f, 0.40f, 0.355f, 0.32f, 0.295f, 0.27f, 0.25f
};

// ---------------------------------------------------------------------------
__global__ void init_kernel()
{
    int i = blockIdx.x * blockDim.x + threadIdx.x;
    if (i < NB * NC * 16) g_rung[i] = 0;
}

// ---------------------------------------------------------------------------
// Pass 1: staged decode + class-major scores + per-(b,c) rung histogram
// (identical to passing R4 version)
// ---------------------------------------------------------------------------
__global__ __launch_bounds__(256) void decode_kernel(
    const float* __restrict__ p5, const float* __restrict__ p4, const float* __restrict__ p3)
{
    __shared__ float s[STG];
    __shared__ float sthr[ANCH];
    __shared__ float sconf[ANCH];
    __shared__ unsigned int shist[NC * 16];

    int blk = blockIdx.x;
    int b = blk / 210;
    int r = blk - b * 210;

    const float* fm;
    int g, layerbase, cellbase, arow;
    float ratio;
    if (r < 10)      { fm = p5; g = 20; layerbase = 0;    cellbase = r * CELLS;        arow = 0; ratio = 32.f; }
    else if (r < 50) { fm = p4; g = 40; layerbase = 1200; cellbase = (r - 10) * CELLS; arow = 3; ratio = 16.f; }
    else             { fm = p3; g = 80; layerbase = 6000; cellbase = (r - 50) * CELLS; arow = 6; ratio = 8.f;  }

    int tid = threadIdx.x;

    const float* src = fm + ((size_t)b * g * g + cellbase) * 255;
    for (int i = tid; i < STG; i += 256) s[i] = src[i];
    for (int i = tid; i < NC * 16; i += 256) shist[i] = 0;
    __syncthreads();

    if (tid < ANCH) {
        int a = tid;
        const float* v = s + a * 85;
        int cellg = cellbase + a / 3;
        int sub = a % 3;
        int xi = cellg % g;
        int yi = cellg / g;

        float t0 = v[0], t1 = v[1], t2 = v[2], t3 = v[3], t4 = v[4];
        float sx = 1.f / (1.f + expf(-t0));
        float sy = 1.f / (1.f + expf(-t1));
        float cx = (sx + (float)xi) * ratio;
        float cy = (sy + (float)yi) * ratio;
        float w = expf(t2) * c_anch[arow + sub][0];
        float h = expf(t3) * c_anch[arow + sub][1];
        float conf = 1.f / (1.f + expf(-t4));

        int gi = layerbase + cellg * 3 + sub;
        g_boxes[b * NA + gi] = make_float4(cx - w * 0.5f, cy - h * 0.5f, cx + w * 0.5f, cy + h * 0.5f);

        float thr;
        if (conf > SCORE_THR) {
            float q = SCORE_THR / conf;
            thr = logf(q / (1.f - q)) - 1e-3f;
        } else {
            thr = __int_as_float(0x7F800000);
        }
        sthr[a] = thr;
        sconf[a] = conf;
    }
    __syncthreads();

    int abase = layerbase + cellbase * 3;
    float* srowb = g_scores + (size_t)b * NC * NA + abase;
    for (int idx = tid; idx < ANCH * NC; idx += 256) {
        int c = idx / ANCH;
        int a = idx - c * ANCH;
        float xc = s[a * 85 + 5 + c];
        float sc = -1.f;
        if (xc > sthr[a]) {
            float v = sconf[a] * (1.f / (1.f + expf(-xc)));
            if (v > SCORE_THR) sc = v;
        }
        srowb[(size_t)c * NA + a] = sc;
        if (sc > 0.f) {
            int ri = 0;
#pragma unroll
            for (int k = 0; k < 16; k++) ri += (sc < c_rungs[k]) ? 1 : 0;
            if (ri > 15) ri = 15;
            atomicAdd(&shist[c * 16 + ri], 1u);
        }
    }
    __syncthreads();

    unsigned int* gr = g_rung + b * NC * 16;
    for (int i = tid; i < NC * 16; i += 256) {
        unsigned v = shist[i];
        if (v) atomicAdd(&gr[i], v);
    }
}

// ---------------------------------------------------------------------------
// Pass 2: per-(image,class) exact top-256 + matrix-based greedy NMS (no
//         barrier loop)
// ---------------------------------------------------------------------------
__global__ __launch_bounds__(256) void nms_kernel()
{
    __shared__ unsigned long long buf[SORTN];       // 8 KB
    __shared__ unsigned int work[NBINS];            // 8 KB: fallback hist, then supp-matrix rows[256][8]
    __shared__ int sscan[256];
    __shared__ unsigned int cnt;
    __shared__ float sT;
    __shared__ int ssn;
    __shared__ int pivot;
    __shared__ float bx1[KPRE], by1[KPRE], bx2[KPRE], by2[KPRE], barea[KPRE];
    __shared__ unsigned int valw[8];
    __shared__ unsigned int remw_s[8];

    int bc = blockIdx.x;
    int b = bc / NC;
    int c = bc - b * NC;
    const float* __restrict__ S = g_scores + ((size_t)b * NC + c) * NA;
    int tid = threadIdx.x;

    if (tid == 0) {
        cnt = 0;
        const unsigned int* gr = g_rung + (size_t)bc * 16;
        int run = 0;
        int j = 15;
        int nj = 0;
#pragma unroll
        for (int k = 0; k < 16; k++) {
            run += (int)gr[k];
            if (run >= KPRE) { j = k; nj = run; break; }
        }
        if (nj == 0) { j = 15; nj = run; }
        sT = c_rungs[j];
        int sn = SORTF;
        if (nj > SORTF) sn = 512;
        if (nj > 512) sn = SORTN;
        ssn = sn;
    }
    __syncthreads();
    float Tj = sT;
    int sn = ssn;

    // single collect pass
    for (int a = tid; a < NA; a += 256) {
        float v = S[a];
        if (v >= Tj) {
            unsigned pos = atomicAdd(&cnt, 1u);
            if (pos < SORTN)
                buf[pos] = ((unsigned long long)__float_as_uint(v) << 32)
                         | (unsigned)(0xFFFFFFFFu - (unsigned)a);
        }
    }
    __syncthreads();

    // rare fallback: > SORTN collected -> exact fine-hist pivot + recollect
    if ((int)cnt > SORTN) {
        float scale = 2047.0f / (1.0f - Tj);
        for (int i = tid; i < NBINS; i += 256) work[i] = 0;
        if (tid == 0) { pivot = 0; cnt = 0; }
        __syncthreads();
        for (int a = tid; a < NA; a += 256) {
            float v = S[a];
            if (v >= Tj) {
                int bin = (int)((v - Tj) * scale);
                if (bin > 2047) bin = 2047;
                atomicAdd(&work[bin], 1u);
            }
        }
        __syncthreads();
        int lc[8];
        int local = 0;
#pragma unroll
        for (int k = 0; k < 8; k++) { lc[k] = (int)work[2047 - (tid * 8 + k)]; local += lc[k]; }
        sscan[tid] = local;
        __syncthreads();
        for (int off = 1; off < 256; off <<= 1) {
            int vv = sscan[tid];
            int u = (tid >= off) ? sscan[tid - off] : 0;
            __syncthreads();
            sscan[tid] = vv + u;
            __syncthreads();
        }
        int incl = sscan[tid];
        int excl = incl - local;
        if (excl < KPRE && incl >= KPRE) {
            int run = excl;
#pragma unroll
            for (int k = 0; k < 8; k++) {
                run += lc[k];
                if (run >= KPRE) { pivot = 2047 - (tid * 8 + k); break; }
            }
        }
        __syncthreads();
        int P = pivot;
        for (int a = tid; a < NA; a += 256) {
            float v = S[a];
            if (v >= Tj) {
                int bin = (int)((v - Tj) * scale);
                if (bin > 2047) bin = 2047;
                if (bin >= P) {
                    unsigned pos = atomicAdd(&cnt, 1u);
                    if (pos < SORTN)
                        buf[pos] = ((unsigned long long)__float_as_uint(v) << 32)
                                 | (unsigned)(0xFFFFFFFFu - (unsigned)a);
                }
            }
        }
        __syncthreads();
        if (tid == 0) ssn = SORTN;
        __syncthreads();
        sn = ssn;
    }

    int m = cnt < (unsigned)sn ? (int)cnt : sn;
    for (int i = tid; i < sn; i += 256)
        if (i >= m) buf[i] = 0ULL;
    __syncthreads();

    // bitonic sort descending, size sn (256/512/1024)
    for (int k = 2; k <= sn; k <<= 1) {
        for (int j = k >> 1; j > 0; j >>= 1) {
            for (int i = tid; i < sn; i += 256) {
                int ixj = i ^ j;
                if (ixj > i) {
                    unsigned long long A = buf[i], Bv = buf[ixj];
                    bool desc = ((i & k) == 0);
                    if (desc ? (A < Bv) : (A > Bv)) { buf[i] = Bv; buf[ixj] = A; }
                }
            }
            __syncthreads();
        }
    }

    // top-256 -> per-thread + smem box arrays
    unsigned long long key = buf[tid];
    bool valid = key != 0ULL;
    float sc = -1.f;
    int a = 0;
    if (valid) {
        sc = __uint_as_float((unsigned)(key >> 32));
        a = (int)(0xFFFFFFFFu - (unsigned)(key & 0xFFFFFFFFu));
    }
    float4 bb = valid ? g_boxes[b * NA + a] : make_float4(0.f, 0.f, 0.f, 0.f);
    float area = fmaxf(bb.z - bb.x, 0.f) * fmaxf(bb.w - bb.y, 0.f);
    bx1[tid] = bb.x; by1[tid] = bb.y; bx2[tid] = bb.z; by2[tid] = bb.w;
    barea[tid] = area;

    unsigned vb = __ballot_sync(0xFFFFFFFFu, valid);
    if ((tid & 31) == 0) { valw[tid >> 5] = vb; remw_s[tid >> 5] = ~vb; }
    __syncthreads();

    // suppression matrix: row tid, bit j set iff j>tid && iou(tid,j) > IOU_THR
    {
        float mx1 = bb.x, my1 = bb.y, mx2 = bb.z, my2 = bb.w, ma = area;
#pragma unroll
        for (int w = 0; w < 8; w++) {
            unsigned bits = 0;
            int jbase = w * 32;
            for (int l = 0; l < 32; l++) {
                int j = jbase + l;
                float iw = fminf(mx2, bx2[j]) - fmaxf(mx1, bx1[j]);
                float ih = fminf(my2, by2[j]) - fmaxf(my1, by1[j]);
                iw = fmaxf(iw, 0.f);
                ih = fmaxf(ih, 0.f);
                float inter = iw * ih;
                float uni = ma + barea[j] - inter;
                float iou = inter / fmaxf(uni, 1e-9f);
                bits |= (j > tid && iou > IOU_THR) ? (1u << l) : 0u;
            }
            work[tid * 8 + w] = bits;
        }
    }
    __syncthreads();

    // greedy scan by warp 0: removed mask in 8 lane registers
    if (tid < 32) {
        unsigned rem = (tid < 8) ? remw_s[tid] : 0u;
        for (int i = 0; i < KPRE; i++) {
            unsigned rw = __shfl_sync(0xFFFFFFFFu, rem, i >> 5);
            if (!((rw >> (i & 31)) & 1u)) {
                if (tid < 8) rem |= work[i * 8 + tid];
            }
        }
        if (tid < 8) remw_s[tid] = rem;
    }
    __syncthreads();

    // keep = valid & !removed, capped at MAXB by inclusive rank
    int w = tid >> 5, bpos = tid & 31;
    unsigned kw = valw[w] & ~remw_s[w];
    bool keep = (kw >> bpos) & 1u;
    if (keep) {
        int rank = __popc(kw & (0xFFFFFFFFu >> (31 - bpos)));
        for (int ww = 0; ww < w; ww++) rank += __popc(valw[ww] & ~remw_s[ww]);
        keep = rank <= MAXB;
    }

    unsigned long long outkey = 0ULL;
    if (keep) {
        int flatpos = c * KPRE + tid;
        unsigned low = ((unsigned)(20479 - flatpos) << 15) | (unsigned)a;
        outkey = ((unsigned long long)__float_as_uint(sc) << 32) | low;
    }
    g_keys[(size_t)b * NC * KPRE + c * KPRE + tid] = outkey;
}

// ---------------------------------------------------------------------------
// Pass 3: per-image top-100 (identical to passing R4 version)
// ---------------------------------------------------------------------------
__global__ __launch_bounds__(256) void final_kernel(float* __restrict__ out)
{
    __shared__ unsigned int hist[NBINS];
    __shared__ unsigned long long buf[SORTF];
    __shared__ int sscan[256];
    __shared__ unsigned int cnt;
    __shared__ int pivot;

    int b = blockIdx.x;
    int tid = threadIdx.x;
    const unsigned long long* K = g_keys + (size_t)b * NC * KPRE;

    for (int i = tid; i < NBINS; i += 256) hist[i] = 0;
    if (tid == 0) { cnt = 0; pivot = 0; }
    __syncthreads();

    for (int i = tid; i < NC * KPRE; i += 256) {
        unsigned long long k = K[i];
        if (k) {
            unsigned bits = (unsigned)(k >> 32);
            unsigned bin = (bits - 0x3E800000u) >> 13;
            if (bin > 2047u) bin = 2047u;
            atomicAdd(&hist[bin], 1u);
        }
    }
    __syncthreads();

    int lc[8];
    int local = 0;
#pragma unroll
    for (int kk = 0; kk < 8; kk++) { lc[kk] = (int)hist[2047 - (tid * 8 + kk)]; local += lc[kk]; }
    sscan[tid] = local;
    __syncthreads();
    for (int off = 1; off < 256; off <<= 1) {
        int vv = sscan[tid];
        int u = (tid >= off) ? sscan[tid - off] : 0;
        __syncthreads();
        sscan[tid] = vv + u;
        __syncthreads();
    }
    int incl = sscan[tid];
    int excl = incl - local;
    if (excl < MAXB && incl >= MAXB) {
        int run = excl;
#pragma unroll
        for (int kk = 0; kk < 8; kk++) {
            run += lc[kk];
            if (run >= MAXB) { pivot = 2047 - (tid * 8 + kk); break; }
        }
    }
    __syncthreads();
    int P = pivot;

    for (int i = tid; i < NC * KPRE; i += 256) {
        unsigned long long k = K[i];
        if (k) {
            unsigned bits = (unsigned)(k >> 32);
            unsigned bin = (bits - 0x3E800000u) >> 13;
            if (bin > 2047u) bin = 2047u;
            if ((int)bin >= P) {
                unsigned pos = atomicAdd(&cnt, 1u);
                if (pos < SORTF) buf[pos] = k;
            }
        }
    }
    __syncthreads();
    int m = cnt < SORTF ? (int)cnt : SORTF;
    for (int i = tid; i < SORTF; i += 256)
        if (i >= m) buf[i] = 0ULL;
    __syncthreads();

    for (int k2 = 2; k2 <= SORTF; k2 <<= 1) {
        for (int j = k2 >> 1; j > 0; j >>= 1) {
            int ixj = tid ^ j;
            if (ixj > tid) {
                unsigned long long A = buf[tid], Bv = buf[ixj];
                bool desc = ((tid & k2) == 0);
                if (desc ? (A < Bv) : (A > Bv)) { buf[tid] = Bv; buf[ixj] = A; }
            }
            __syncthreads();
        }
    }

    if (tid < MAXB) {
        unsigned long long k = buf[tid];
        float x1 = -1.f, y1 = -1.f, x2 = -1.f, y2 = -1.f, scv = -1.f, lab = -1.f;
        if (k) {
            unsigned bits = (unsigned)(k >> 32);
            scv = __uint_as_float(bits);
            unsigned low = (unsigned)(k & 0xFFFFFFFFu);
            int flatpos = 20479 - (int)(low >> 15);
            int a = (int)(low & 0x7FFFu);
            int cls = flatpos >> 8;
            float4 bb = g_boxes[b * NA + a];
            x1 = bb.x; y1 = bb.y; x2 = bb.z; y2 = bb.w;
            lab = (float)cls;
        }
        float* ob = out;
        float* os = out + NB * MAXB * 4;
        float* ol = out + NB * MAXB * 5;
        ob[(b * MAXB + tid) * 4 + 0] = x1;
        ob[(b * MAXB + tid) * 4 + 1] = y1;
        ob[(b * MAXB + tid) * 4 + 2] = x2;
        ob[(b * MAXB + tid) * 4 + 3] = y2;
        os[b * MAXB + tid] = scv;
        ol[b * MAXB + tid] = lab;
    }
}

// ---------------------------------------------------------------------------
extern "C" void kernel_launch(void* const* d_in, const int* in_sizes, int n_in,
                              void* d_out, int out_size)
{
    const float* p5 = (const float*)d_in[0];
    const float* p4 = (const float*)d_in[1];
    const float* p3 = (const float*)d_in[2];
    float* out = (float*)d_out;

    init_kernel<<<(NB * NC * 16 + 255) / 256, 256>>>();
    decode_kernel<<<NB * 210, 256>>>(p5, p4, p3);
    nms_kernel<<<NB * NC, 256>>>();
    final_kernel<<<NB, 256>>>(out);
}

// round 6
// speedup vs baseline: 1.1232x; 1.1232x over previous
#include <cuda_runtime.h>
#include <math.h>
#include <stdint.h>

#define NB 16
#define NA 25200
#define NC 80
#define KPRE 256
#define MAXB 100
#define SORTN 1024
#define SORTF 256
#define NBINS 2048
#define SCORE_THR 0.25f
#define IOU_THR 0.1f

#define DECBLK 99   // ceil(25200/256) blocks per image

// anchors: p5 (20x20) [0,1200), p4 (40x40) [1200,6000), p3 (80x80) [6000,25200)

__device__ float4 g_boxes[NB * NA];
__device__ float g_scores[(size_t)NB * NC * NA];
__device__ unsigned int g_rung[NB * NC * 16];
__device__ unsigned long long g_keys[NB * NC * KPRE];

__constant__ float c_anch[9][2] = {
    {116.f, 90.f}, {156.f, 198.f}, {373.f, 326.f},
    {30.f, 61.f},  {62.f, 45.f},   {59.f, 119.f},
    {10.f, 13.f},  {16.f, 30.f},   {33.f, 23.f}
};

__constant__ float c_rungs[16] = {
    0.97f, 0.93f, 0.88f, 0.82f, 0.76f, 0.70f, 0.64f, 0.58f,
    0.52f, 0.46f, 0.40f, 0.355f, 0.32f, 0.295f, 0.27f, 0.25f
};

// ---------------------------------------------------------------------------
__global__ void init_kernel()
{
    int i = blockIdx.x * blockDim.x + threadIdx.x;
    if (i < NB * NC * 16) g_rung[i] = 0;
}

// ---------------------------------------------------------------------------
// Pass 1: decode (R1-style, one thread per anchor) + class-major scores
//         + fused per-(b,c) rung histogram. Block serves ONE image.
// ---------------------------------------------------------------------------
__global__ __launch_bounds__(256) void decode_kernel(
    const float* __restrict__ p5, const float* __restrict__ p4, const float* __restrict__ p3)
{
    __shared__ unsigned int shist[NC * 16];   // 5120 B

    int tid = threadIdx.x;
    int b = blockIdx.x / DECBLK;
    int blk = blockIdx.x - b * DECBLK;
    int gi = blk * 256 + tid;
    bool act = gi < NA;

    for (int i = tid; i < NC * 16; i += 256) shist[i] = 0;
    __syncthreads();

    float conf = 0.f;
    float thr = __int_as_float(0x7F800000);
    const float* v = 0;

    if (act) {
        int layer, base, g;
        const float* fm;
        float ratio;
        if (gi < 1200)      { layer = 0; base = 0;    g = 20; fm = p5; ratio = 32.f; }
        else if (gi < 6000) { layer = 1; base = 1200; g = 40; fm = p4; ratio = 16.f; }
        else                { layer = 2; base = 6000; g = 80; fm = p3; ratio = 8.f;  }

        int li = gi - base;
        int cell = li / 3;
        int a = li - cell * 3;
        int xi = cell % g;
        int yi = cell / g;
        v = fm + ((size_t)(b * g + yi) * g + xi) * 255 + a * 85;

        float t0 = v[0], t1 = v[1], t2 = v[2], t3 = v[3], t4 = v[4];
        float sx = 1.f / (1.f + expf(-t0));
        float sy = 1.f / (1.f + expf(-t1));
        float cx = (sx + (float)xi) * ratio;
        float cy = (sy + (float)yi) * ratio;
        float w = expf(t2) * c_anch[layer * 3 + a][0];
        float h = expf(t3) * c_anch[layer * 3 + a][1];
        conf = 1.f / (1.f + expf(-t4));

        g_boxes[b * NA + gi] = make_float4(cx - w * 0.5f, cy - h * 0.5f, cx + w * 0.5f, cy + h * 0.5f);

        if (conf > SCORE_THR) {
            float q = SCORE_THR / conf;
            thr = logf(q / (1.f - q)) - 1e-3f;
        }
    }

    float* srow = g_scores + (size_t)b * NC * NA + gi;
#pragma unroll
    for (int c = 0; c < NC; c++) {
        if (act) {
            float xc = v[5 + c];
            float s = -1.f;
            if (xc > thr) {
                float sc = conf * (1.f / (1.f + expf(-xc)));
                if (sc > SCORE_THR) s = sc;
            }
            srow[(size_t)c * NA] = s;
            if (s > 0.f) {
                int ri = 0;
#pragma unroll
                for (int k = 0; k < 16; k++) ri += (s < c_rungs[k]) ? 1 : 0;
                if (ri > 15) ri = 15;
                atomicAdd(&shist[c * 16 + ri], 1u);
            }
        }
    }
    __syncthreads();

    unsigned int* gr = g_rung + b * NC * 16;
    for (int i = tid; i < NC * 16; i += 256) {
        unsigned u = shist[i];
        if (u) atomicAdd(&gr[i], u);
    }
}

// ---------------------------------------------------------------------------
// Pass 2: per-(image,class) exact top-256 (rung threshold -> single float4
//         collect -> dynamic bitonic) + barrier-loop greedy NMS (R4 form)
// ---------------------------------------------------------------------------
__global__ __launch_bounds__(256) void nms_kernel()
{
    __shared__ unsigned long long buf[SORTN];
    __shared__ int sscan[256];
    __shared__ unsigned int cnt;
    __shared__ float sT;
    __shared__ int ssn;
    __shared__ unsigned int hist[NBINS];   // fallback only
    __shared__ int pivot;
    __shared__ float bx1[KPRE], by1[KPRE], bx2[KPRE], by2[KPRE], barea[KPRE], bscore[KPRE];
    __shared__ int banch[KPRE];
    __shared__ int supp[KPRE];

    int bc = blockIdx.x;
    int b = bc / NC;
    int c = bc - b * NC;
    const float4* __restrict__ S4 =
        (const float4*)(g_scores + ((size_t)b * NC + c) * NA);
    const float* __restrict__ S = (const float*)S4;
    int tid = threadIdx.x;

    if (tid == 0) {
        cnt = 0;
        const unsigned int* gr = g_rung + (size_t)bc * 16;
        int run = 0;
        int j = 15;
        int nj = 0;
#pragma unroll
        for (int k = 0; k < 16; k++) {
            run += (int)gr[k];
            if (run >= KPRE) { j = k; nj = run; break; }
        }
        if (nj == 0) { j = 15; nj = run; }
        sT = c_rungs[j];
        int sn = SORTF;
        if (nj > SORTF) sn = 512;
        if (nj > 512) sn = SORTN;
        ssn = sn;
    }
    __syncthreads();
    float Tj = sT;
    int sn = ssn;

    // single collect pass, float4 (NA/4 = 6300 exactly)
    for (int i4 = tid; i4 < NA / 4; i4 += 256) {
        float4 q = S4[i4];
#pragma unroll
        for (int k = 0; k < 4; k++) {
            float vv = (k == 0) ? q.x : (k == 1) ? q.y : (k == 2) ? q.z : q.w;
            if (vv >= Tj) {
                int a = i4 * 4 + k;
                unsigned pos = atomicAdd(&cnt, 1u);
                if (pos < SORTN)
                    buf[pos] = ((unsigned long long)__float_as_uint(vv) << 32)
                             | (unsigned)(0xFFFFFFFFu - (unsigned)a);
            }
        }
    }
    __syncthreads();

    // rare fallback: > SORTN collected -> exact fine-hist pivot + recollect
    if ((int)cnt > SORTN) {
        float scale = 2047.0f / (1.0f - Tj);
        for (int i = tid; i < NBINS; i += 256) hist[i] = 0;
        if (tid == 0) { pivot = 0; cnt = 0; }
        __syncthreads();
        for (int a = tid; a < NA; a += 256) {
            float vv = S[a];
            if (vv >= Tj) {
                int bin = (int)((vv - Tj) * scale);
                if (bin > 2047) bin = 2047;
                atomicAdd(&hist[bin], 1u);
            }
        }
        __syncthreads();
        int lc[8];
        int local = 0;
#pragma unroll
        for (int k = 0; k < 8; k++) { lc[k] = (int)hist[2047 - (tid * 8 + k)]; local += lc[k]; }
        sscan[tid] = local;
        __syncthreads();
        for (int off = 1; off < 256; off <<= 1) {
            int vv = sscan[tid];
            int u = (tid >= off) ? sscan[tid - off] : 0;
            __syncthreads();
            sscan[tid] = vv + u;
            __syncthreads();
        }
        int incl = sscan[tid];
        int excl = incl - local;
        if (excl < KPRE && incl >= KPRE) {
            int run = excl;
#pragma unroll
            for (int k = 0; k < 8; k++) {
                run += lc[k];
                if (run >= KPRE) { pivot = 2047 - (tid * 8 + k); break; }
            }
        }
        __syncthreads();
        int P = pivot;
        for (int a = tid; a < NA; a += 256) {
            float vv = S[a];
            if (vv >= Tj) {
                int bin = (int)((vv - Tj) * scale);
                if (bin > 2047) bin = 2047;
                if (bin >= P) {
                    unsigned pos = atomicAdd(&cnt, 1u);
                    if (pos < SORTN)
                        buf[pos] = ((unsigned long long)__float_as_uint(vv) << 32)
                                 | (unsigned)(0xFFFFFFFFu - (unsigned)a);
                }
            }
        }
        __syncthreads();
        if (tid == 0) ssn = SORTN;
        __syncthreads();
        sn = ssn;
    }

    int m = cnt < (unsigned)sn ? (int)cnt : sn;
    for (int i = tid; i < sn; i += 256)
        if (i >= m) buf[i] = 0ULL;
    __syncthreads();

    // bitonic sort descending, size sn (256/512/1024)
    for (int k = 2; k <= sn; k <<= 1) {
        for (int j = k >> 1; j > 0; j >>= 1) {
            for (int i = tid; i < sn; i += 256) {
                int ixj = i ^ j;
                if (ixj > i) {
                    unsigned long long A = buf[i], Bv = buf[ixj];
                    bool desc = ((i & k) == 0);
                    if (desc ? (A < Bv) : (A > Bv)) { buf[i] = Bv; buf[ixj] = A; }
                }
            }
            __syncthreads();
        }
    }

    // top-256 -> smem box arrays
    unsigned long long key = buf[tid];
    bool valid = key != 0ULL;
    float sc;
    int a;
    if (valid) {
        sc = __uint_as_float((unsigned)(key >> 32));
        a = (int)(0xFFFFFFFFu - (unsigned)(key & 0xFFFFFFFFu));
    } else {
        sc = -1.f;
        a = 0;
    }
    float4 bb = valid ? g_boxes[b * NA + a] : make_float4(0.f, 0.f, 0.f, 0.f);
    bx1[tid] = bb.x; by1[tid] = bb.y; bx2[tid] = bb.z; by2[tid] = bb.w;
    float area = fmaxf(bb.z - bb.x, 0.f) * fmaxf(bb.w - bb.y, 0.f);
    barea[tid] = area;
    bscore[tid] = sc;
    banch[tid] = a;
    supp[tid] = valid ? 0 : 1;
    __syncthreads();

    // greedy NMS barrier loop (exact ref IoU formula)
    float mx1 = bb.x, my1 = bb.y, mx2 = bb.z, my2 = bb.w, ma = area;
    bool msupp = !valid;
    for (int i = 0; i < KPRE - 1; i++) {
        if (!supp[i] && tid > i && !msupp) {
            float iw = fminf(mx2, bx2[i]) - fmaxf(mx1, bx1[i]);
            float ih = fminf(my2, by2[i]) - fmaxf(my1, by1[i]);
            iw = fmaxf(iw, 0.f);
            ih = fmaxf(ih, 0.f);
            float inter = iw * ih;
            float uni = ma + barea[i] - inter;
            float iou = inter / fmaxf(uni, 1e-9f);
            if (iou > IOU_THR) { msupp = true; supp[tid] = 1; }
        }
        __syncthreads();
    }

    // keep + cumsum cap at MAXB
    int keep = msupp ? 0 : 1;
    sscan[tid] = keep;
    __syncthreads();
    for (int off = 1; off < 256; off <<= 1) {
        int vv = sscan[tid];
        int u = (tid >= off) ? sscan[tid - off] : 0;
        __syncthreads();
        sscan[tid] = vv + u;
        __syncthreads();
    }
    int rank = sscan[tid];
    keep = keep && (rank <= MAXB);

    unsigned long long outkey = 0ULL;
    if (keep) {
        int flatpos = c * KPRE + tid;
        unsigned low = ((unsigned)(20479 - flatpos) << 15) | (unsigned)banch[tid];
        outkey = ((unsigned long long)__float_as_uint(bscore[tid]) << 32) | low;
    }
    g_keys[(size_t)b * NC * KPRE + c * KPRE + tid] = outkey;
}

// ---------------------------------------------------------------------------
// Pass 3: per-image top-100 (identical to passing R4 version)
// ---------------------------------------------------------------------------
__global__ __launch_bounds__(256) void final_kernel(float* __restrict__ out)
{
    __shared__ unsigned int hist[NBINS];
    __shared__ unsigned long long buf[SORTF];
    __shared__ int sscan[256];
    __shared__ unsigned int cnt;
    __shared__ int pivot;

    int b = blockIdx.x;
    int tid = threadIdx.x;
    const unsigned long long* K = g_keys + (size_t)b * NC * KPRE;

    for (int i = tid; i < NBINS; i += 256) hist[i] = 0;
    if (tid == 0) { cnt = 0; pivot = 0; }
    __syncthreads();

    for (int i = tid; i < NC * KPRE; i += 256) {
        unsigned long long k = K[i];
        if (k) {
            unsigned bits = (unsigned)(k >> 32);
            unsigned bin = (bits - 0x3E800000u) >> 13;
            if (bin > 2047u) bin = 2047u;
            atomicAdd(&hist[bin], 1u);
        }
    }
    __syncthreads();

    int lc[8];
    int local = 0;
#pragma unroll
    for (int kk = 0; kk < 8; kk++) { lc[kk] = (int)hist[2047 - (tid * 8 + kk)]; local += lc[kk]; }
    sscan[tid] = local;
    __syncthreads();
    for (int off = 1; off < 256; off <<= 1) {
        int vv = sscan[tid];
        int u = (tid >= off) ? sscan[tid - off] : 0;
        __syncthreads();
        sscan[tid] = vv + u;
        __syncthreads();
    }
    int incl = sscan[tid];
    int excl = incl - local;
    if (excl < MAXB && incl >= MAXB) {
        int run = excl;
#pragma unroll
        for (int kk = 0; kk < 8; kk++) {
            run += lc[kk];
            if (run >= MAXB) { pivot = 2047 - (tid * 8 + kk); break; }
        }
    }
    __syncthreads();
    int P = pivot;

    for (int i = tid; i < NC * KPRE; i += 256) {
        unsigned long long k = K[i];
        if (k) {
            unsigned bits = (unsigned)(k >> 32);
            unsigned bin = (bits - 0x3E800000u) >> 13;
            if (bin > 2047u) bin = 2047u;
            if ((int)bin >= P) {
                unsigned pos = atomicAdd(&cnt, 1u);
                if (pos < SORTF) buf[pos] = k;
            }
        }
    }
    __syncthreads();
    int m = cnt < SORTF ? (int)cnt : SORTF;
    for (int i = tid; i < SORTF; i += 256)
        if (i >= m) buf[i] = 0ULL;
    __syncthreads();

    for (int k2 = 2; k2 <= SORTF; k2 <<= 1) {
        for (int j = k2 >> 1; j > 0; j >>= 1) {
            int ixj = tid ^ j;
            if (ixj > tid) {
                unsigned long long A = buf[tid], Bv = buf[ixj];
                bool desc = ((tid & k2) == 0);
                if (desc ? (A < Bv) : (A > Bv)) { buf[tid] = Bv; buf[ixj] = A; }
            }
            __syncthreads();
        }
    }

    if (tid < MAXB) {
        unsigned long long k = buf[tid];
        float x1 = -1.f, y1 = -1.f, x2 = -1.f, y2 = -1.f, scv = -1.f, lab = -1.f;
        if (k) {
            unsigned bits = (unsigned)(k >> 32);
            scv = __uint_as_float(bits);
            unsigned low = (unsigned)(k & 0xFFFFFFFFu);
            int flatpos = 20479 - (int)(low >> 15);
            int a = (int)(low & 0x7FFFu);
            int cls = flatpos >> 8;
            float4 bb = g_boxes[b * NA + a];
            x1 = bb.x; y1 = bb.y; x2 = bb.z; y2 = bb.w;
            lab = (float)cls;
        }
        float* ob = out;
        float* os = out + NB * MAXB * 4;
        float* ol = out + NB * MAXB * 5;
        ob[(b * MAXB + tid) * 4 + 0] = x1;
        ob[(b * MAXB + tid) * 4 + 1] = y1;
        ob[(b * MAXB + tid) * 4 + 2] = x2;
        ob[(b * MAXB + tid) * 4 + 3] = y2;
        os[b * MAXB + tid] = scv;
        ol[b * MAXB + tid] = lab;
    }
}

// ---------------------------------------------------------------------------
extern "C" void kernel_launch(void* const* d_in, const int* in_sizes, int n_in,
                              void* d_out, int out_size)
{
    const float* p5 = (const float*)d_in[0];
    const float* p4 = (const float*)d_in[1];
    const float* p3 = (const float*)d_in[2];
    float* out = (float*)d_out;

    init_kernel<<<(NB * NC * 16 + 255) / 256, 256>>>();
    decode_kernel<<<NB * DECBLK, 256>>>(p5, p4, p3);
    nms_kernel<<<NB * NC, 256>>>();
    final_kernel<<<NB, 256>>>(out);
}

// round 7
// speedup vs baseline: 1.3057x; 1.1625x over previous
#include <cuda_runtime.h>
#include <math.h>
#include <stdint.h>

#define NB 16
#define NA 25200
#define NC 80
#define KPRE 256
#define MAXB 100
#define CAPB 2048
#define SORTF 256
#define NBINS 2048
#define SCORE_THR 0.25f
#define IOU_THR 0.1f
#define T0 0.58f

#define DECBLK 99   // ceil(25200/256) blocks per image

// anchors: p5 (20x20) [0,1200), p4 (40x40) [1200,6000), p3 (80x80) [6000,25200)

__device__ float4 g_boxes[NB * NA];
__device__ unsigned long long g_bucket[(size_t)NB * NC * CAPB];   // 21 MB
__device__ unsigned int g_bcount[NB * NC];
__device__ float g_fbrow[(size_t)NB * NC * NA];                   // fallback scratch (written only on fallback)
__device__ unsigned long long g_keys[NB * NC * KPRE];

__constant__ float c_anch[9][2] = {
    {116.f, 90.f}, {156.f, 198.f}, {373.f, 326.f},
    {30.f, 61.f},  {62.f, 45.f},   {59.f, 119.f},
    {10.f, 13.f},  {16.f, 30.f},   {33.f, 23.f}
};

// ---------------------------------------------------------------------------
__global__ void init_kernel()
{
    int i = blockIdx.x * blockDim.x + threadIdx.x;
    if (i < NB * NC) g_bcount[i] = 0;
}

// ---------------------------------------------------------------------------
// layer geometry for a flat anchor index
__device__ __forceinline__ const float* anchor_ptr(
    const float* p5, const float* p4, const float* p3,
    int b, int gi, int& layer, int& g, float& ratio, int& xi, int& yi, int& sub)
{
    const float* fm;
    int base;
    if (gi < 1200)      { layer = 0; base = 0;    g = 20; fm = p5; ratio = 32.f; }
    else if (gi < 6000) { layer = 1; base = 1200; g = 40; fm = p4; ratio = 16.f; }
    else                { layer = 2; base = 6000; g = 80; fm = p3; ratio = 8.f;  }
    int li = gi - base;
    int cell = li / 3;
    sub = li - cell * 3;
    xi = cell % g;
    yi = cell / g;
    return fm + ((size_t)(b * g + yi) * g + xi) * 255 + sub * 85;
}

// ---------------------------------------------------------------------------
// Pass 1: decode boxes + scatter keys with score >= T0 into per-(b,c) buckets
// ---------------------------------------------------------------------------
__global__ __launch_bounds__(256) void decode_kernel(
    const float* __restrict__ p5, const float* __restrict__ p4, const float* __restrict__ p3)
{
    int tid = threadIdx.x;
    int b = blockIdx.x / DECBLK;
    int blk = blockIdx.x - b * DECBLK;
    int gi = blk * 256 + tid;
    if (gi >= NA) return;

    int layer, g, xi, yi, sub;
    float ratio;
    const float* v = anchor_ptr(p5, p4, p3, b, gi, layer, g, ratio, xi, yi, sub);

    float t0 = v[0], t1 = v[1], t2 = v[2], t3 = v[3], t4 = v[4];
    float sx = 1.f / (1.f + expf(-t0));
    float sy = 1.f / (1.f + expf(-t1));
    float cx = (sx + (float)xi) * ratio;
    float cy = (sy + (float)yi) * ratio;
    float w = expf(t2) * c_anch[layer * 3 + sub][0];
    float h = expf(t3) * c_anch[layer * 3 + sub][1];
    float conf = 1.f / (1.f + expf(-t4));

    g_boxes[b * NA + gi] = make_float4(cx - w * 0.5f, cy - h * 0.5f, cx + w * 0.5f, cy + h * 0.5f);

    // logit-space screen for score >= T0 (conservative margin, exact recheck)
    float thr = __int_as_float(0x7F800000);
    if (conf > T0) {
        float q = T0 / conf;
        thr = logf(q / (1.f - q)) - 1e-3f;
    }

#pragma unroll
    for (int c = 0; c < NC; c++) {
        float xc = v[5 + c];
        if (xc > thr) {
            float sc = conf * (1.f / (1.f + expf(-xc)));
            if (sc >= T0) {
                int bkt = b * NC + c;
                unsigned pos = atomicAdd(&g_bcount[bkt], 1u);
                if (pos < CAPB)
                    g_bucket[(size_t)bkt * CAPB + pos] =
                        ((unsigned long long)__float_as_uint(sc) << 32)
                        | (unsigned)(0xFFFFFFFFu - (unsigned)gi);
            }
        }
    }
}

// ---------------------------------------------------------------------------
// Pass 2: per-(image,class) exact top-256 from bucket + greedy NMS.
// Fallback (count<256 or >CAPB): recompute row exactly, hist-pivot, collect.
// ---------------------------------------------------------------------------
__global__ __launch_bounds__(256) void nms_kernel(
    const float* __restrict__ p5, const float* __restrict__ p4, const float* __restrict__ p3)
{
    __shared__ unsigned long long buf[CAPB];     // 16 KB; upper 8 KB aliased as fallback hist
    __shared__ int sscan[256];
    __shared__ unsigned int cnt;
    __shared__ int pivot;
    __shared__ float bx1[KPRE], by1[KPRE], bx2[KPRE], by2[KPRE], barea[KPRE], bscore[KPRE];
    __shared__ int banch[KPRE];
    __shared__ int supp[KPRE];

    int bc = blockIdx.x;
    int b = bc / NC;
    int c = bc - b * NC;
    int tid = threadIdx.x;

    unsigned n_raw = g_bcount[bc];
    int sn;

    if (n_raw >= KPRE && n_raw <= CAPB) {
        // ---- fast path: bucket holds all candidates >= T0, count >= 256 ----
        int sp = SORTF;
        while (sp < (int)n_raw) sp <<= 1;      // 256/512/1024/2048
        sn = sp;
        const unsigned long long* BK = g_bucket + (size_t)bc * CAPB;
        for (int i = tid; i < sn; i += 256)
            buf[i] = (i < (int)n_raw) ? BK[i] : 0ULL;
        __syncthreads();
    } else {
        // ---- exact fallback: recompute row, hist-pivot, collect ----
        float* row = g_fbrow + (size_t)bc * NA;
        unsigned int* hist = (unsigned int*)(buf + 1024);   // 2048 uints = 8 KB upper half
        for (int i = tid; i < NBINS; i += 256) hist[i] = 0;
        if (tid == 0) { cnt = 0; pivot = 0; }
        __syncthreads();

        for (int gi = tid; gi < NA; gi += 256) {
            int layer, g, xi, yi, sub;
            float ratio;
            const float* v = anchor_ptr(p5, p4, p3, b, gi, layer, g, ratio, xi, yi, sub);
            float conf = 1.f / (1.f + expf(-v[4]));
            float sc = conf * (1.f / (1.f + expf(-v[5 + c])));
            float s = (sc > SCORE_THR) ? sc : -1.f;
            row[gi] = s;
            if (s > 0.f) {
                unsigned bits = __float_as_uint(s);
                unsigned bin = (bits - 0x3E800000u) >> 13;
                if (bin > 2047u) bin = 2047u;
                atomicAdd(&hist[bin], 1u);
            }
        }
        __syncthreads();

        int lc[8];
        int local = 0;
#pragma unroll
        for (int k = 0; k < 8; k++) { lc[k] = (int)hist[2047 - (tid * 8 + k)]; local += lc[k]; }
        sscan[tid] = local;
        __syncthreads();
        for (int off = 1; off < 256; off <<= 1) {
            int vv = sscan[tid];
            int u = (tid >= off) ? sscan[tid - off] : 0;
            __syncthreads();
            sscan[tid] = vv + u;
            __syncthreads();
        }
        int incl = sscan[tid];
        int excl = incl - local;
        if (excl < KPRE && incl >= KPRE) {
            int run = excl;
#pragma unroll
            for (int k = 0; k < 8; k++) {
                run += lc[k];
                if (run >= KPRE) { pivot = 2047 - (tid * 8 + k); break; }
            }
        }
        __syncthreads();
        int P = pivot;

        for (int gi = tid; gi < NA; gi += 256) {
            float s = row[gi];
            if (s > 0.f) {
                unsigned bits = __float_as_uint(s);
                unsigned bin = (bits - 0x3E800000u) >> 13;
                if (bin > 2047u) bin = 2047u;
                if ((int)bin >= P) {
                    unsigned pos = atomicAdd(&cnt, 1u);
                    if (pos < 1024)
                        buf[pos] = ((unsigned long long)bits << 32)
                                 | (unsigned)(0xFFFFFFFFu - (unsigned)gi);
                }
            }
        }
        __syncthreads();
        sn = 1024;
        int m = cnt < 1024u ? (int)cnt : 1024;
        for (int i = tid; i < sn; i += 256)
            if (i >= m) buf[i] = 0ULL;
        __syncthreads();
    }

    // bitonic sort descending, size sn
    for (int k = 2; k <= sn; k <<= 1) {
        for (int j = k >> 1; j > 0; j >>= 1) {
            for (int i = tid; i < sn; i += 256) {
                int ixj = i ^ j;
                if (ixj > i) {
                    unsigned long long A = buf[i], Bv = buf[ixj];
                    bool desc = ((i & k) == 0);
                    if (desc ? (A < Bv) : (A > Bv)) { buf[i] = Bv; buf[ixj] = A; }
                }
            }
            __syncthreads();
        }
    }

    // top-256 -> smem box arrays
    unsigned long long key = buf[tid];
    bool valid = key != 0ULL;
    float sc;
    int a;
    if (valid) {
        sc = __uint_as_float((unsigned)(key >> 32));
        a = (int)(0xFFFFFFFFu - (unsigned)(key & 0xFFFFFFFFu));
    } else {
        sc = -1.f;
        a = 0;
    }
    float4 bb = valid ? g_boxes[b * NA + a] : make_float4(0.f, 0.f, 0.f, 0.f);
    bx1[tid] = bb.x; by1[tid] = bb.y; bx2[tid] = bb.z; by2[tid] = bb.w;
    float area = fmaxf(bb.z - bb.x, 0.f) * fmaxf(bb.w - bb.y, 0.f);
    barea[tid] = area;
    bscore[tid] = sc;
    banch[tid] = a;
    supp[tid] = valid ? 0 : 1;
    __syncthreads();

    // greedy NMS barrier loop (exact ref IoU formula)
    float mx1 = bb.x, my1 = bb.y, mx2 = bb.z, my2 = bb.w, ma = area;
    bool msupp = !valid;
    for (int i = 0; i < KPRE - 1; i++) {
        if (!supp[i] && tid > i && !msupp) {
            float iw = fminf(mx2, bx2[i]) - fmaxf(mx1, bx1[i]);
            float ih = fminf(my2, by2[i]) - fmaxf(my1, by1[i]);
            iw = fmaxf(iw, 0.f);
            ih = fmaxf(ih, 0.f);
            float inter = iw * ih;
            float uni = ma + barea[i] - inter;
            float iou = inter / fmaxf(uni, 1e-9f);
            if (iou > IOU_THR) { msupp = true; supp[tid] = 1; }
        }
        __syncthreads();
    }

    // keep + cumsum cap at MAXB
    int keep = msupp ? 0 : 1;
    sscan[tid] = keep;
    __syncthreads();
    for (int off = 1; off < 256; off <<= 1) {
        int vv = sscan[tid];
        int u = (tid >= off) ? sscan[tid - off] : 0;
        __syncthreads();
        sscan[tid] = vv + u;
        __syncthreads();
    }
    int rank = sscan[tid];
    keep = keep && (rank <= MAXB);

    unsigned long long outkey = 0ULL;
    if (keep) {
        int flatpos = c * KPRE + tid;
        unsigned low = ((unsigned)(20479 - flatpos) << 15) | (unsigned)banch[tid];
        outkey = ((unsigned long long)__float_as_uint(bscore[tid]) << 32) | low;
    }
    g_keys[(size_t)b * NC * KPRE + c * KPRE + tid] = outkey;
}

// ---------------------------------------------------------------------------
// Pass 3: per-image top-100 (proven form)
// ---------------------------------------------------------------------------
__global__ __launch_bounds__(256) void final_kernel(float* __restrict__ out)
{
    __shared__ unsigned int hist[NBINS];
    __shared__ unsigned long long buf[SORTF];
    __shared__ int sscan[256];
    __shared__ unsigned int cnt;
    __shared__ int pivot;

    int b = blockIdx.x;
    int tid = threadIdx.x;
    const unsigned long long* K = g_keys + (size_t)b * NC * KPRE;

    for (int i = tid; i < NBINS; i += 256) hist[i] = 0;
    if (tid == 0) { cnt = 0; pivot = 0; }
    __syncthreads();

    for (int i = tid; i < NC * KPRE; i += 256) {
        unsigned long long k = K[i];
        if (k) {
            unsigned bits = (unsigned)(k >> 32);
            unsigned bin = (bits - 0x3E800000u) >> 13;
            if (bin > 2047u) bin = 2047u;
            atomicAdd(&hist[bin], 1u);
        }
    }
    __syncthreads();

    int lc[8];
    int local = 0;
#pragma unroll
    for (int kk = 0; kk < 8; kk++) { lc[kk] = (int)hist[2047 - (tid * 8 + kk)]; local += lc[kk]; }
    sscan[tid] = local;
    __syncthreads();
    for (int off = 1; off < 256; off <<= 1) {
        int vv = sscan[tid];
        int u = (tid >= off) ? sscan[tid - off] : 0;
        __syncthreads();
        sscan[tid] = vv + u;
        __syncthreads();
    }
    int incl = sscan[tid];
    int excl = incl - local;
    if (excl < MAXB && incl >= MAXB) {
        int run = excl;
#pragma unroll
        for (int kk = 0; kk < 8; kk++) {
            run += lc[kk];
            if (run >= MAXB) { pivot = 2047 - (tid * 8 + kk); break; }
        }
    }
    __syncthreads();
    int P = pivot;

    for (int i = tid; i < NC * KPRE; i += 256) {
        unsigned long long k = K[i];
        if (k) {
            unsigned bits = (unsigned)(k >> 32);
            unsigned bin = (bits - 0x3E800000u) >> 13;
            if (bin > 2047u) bin = 2047u;
            if ((int)bin >= P) {
                unsigned pos = atomicAdd(&cnt, 1u);
                if (pos < SORTF) buf[pos] = k;
            }
        }
    }
    __syncthreads();
    int m = cnt < SORTF ? (int)cnt : SORTF;
    for (int i = tid; i < SORTF; i += 256)
        if (i >= m) buf[i] = 0ULL;
    __syncthreads();

    for (int k2 = 2; k2 <= SORTF; k2 <<= 1) {
        for (int j = k2 >> 1; j > 0; j >>= 1) {
            int ixj = tid ^ j;
            if (ixj > tid) {
                unsigned long long A = buf[tid], Bv = buf[ixj];
                bool desc = ((tid & k2) == 0);
                if (desc ? (A < Bv) : (A > Bv)) { buf[tid] = Bv; buf[ixj] = A; }
            }
            __syncthreads();
        }
    }

    if (tid < MAXB) {
        unsigned long long k = buf[tid];
        float x1 = -1.f, y1 = -1.f, x2 = -1.f, y2 = -1.f, scv = -1.f, lab = -1.f;
        if (k) {
            unsigned bits = (unsigned)(k >> 32);
            scv = __uint_as_float(bits);
            unsigned low = (unsigned)(k & 0xFFFFFFFFu);
            int flatpos = 20479 - (int)(low >> 15);
            int a = (int)(low & 0x7FFFu);
            int cls = flatpos >> 8;
            float4 bb = g_boxes[b * NA + a];
            x1 = bb.x; y1 = bb.y; x2 = bb.z; y2 = bb.w;
            lab = (float)cls;
        }
        float* ob = out;
        float* os = out + NB * MAXB * 4;
        float* ol = out + NB * MAXB * 5;
        ob[(b * MAXB + tid) * 4 + 0] = x1;
        ob[(b * MAXB + tid) * 4 + 1] = y1;
        ob[(b * MAXB + tid) * 4 + 2] = x2;
        ob[(b * MAXB + tid) * 4 + 3] = y2;
        os[b * MAXB + tid] = scv;
        ol[b * MAXB + tid] = lab;
    }
}

// ---------------------------------------------------------------------------
extern "C" void kernel_launch(void* const* d_in, const int* in_sizes, int n_in,
                              void* d_out, int out_size)
{
    const float* p5 = (const float*)d_in[0];
    const float* p4 = (const float*)d_in[1];
    const float* p3 = (const float*)d_in[2];
    float* out = (float*)d_out;

    init_kernel<<<(NB * NC + 255) / 256, 256>>>();
    decode_kernel<<<NB * DECBLK, 256>>>(p5, p4, p3);
    nms_kernel<<<NB * NC, 256>>>(p5, p4, p3);
    final_kernel<<<NB, 256>>>(out);
}